// round 8
// baseline (speedup 1.0000x reference)
#include <cuda_runtime.h>
#include <cstdint>

#define NPTS 262144
#define CCLS 10
#define DFEAT 64
#define TTRI 4096

#define NTHR 256
#define NBLK 1024
#define ROWS_PER_BLK 256                       // 1024 * 256 = NPTS exact
#define CE_BYTES (ROWS_PER_BLK * CCLS * 4)     // 10240 B per array per block
#define MSE_PER_BLK 192                        // 1024 * 192 = 196608 = 3N/4 exact

__device__ float    g_partials[NBLK];
__device__ unsigned g_count;                   // zero-init; self-resetting

__device__ __forceinline__ uint32_t smem_u32(const void* p) {
    uint32_t a;
    asm("{ .reg .u64 t; cvta.to.shared.u64 t, %1; cvt.u32.u64 %0, t; }"
        : "=r"(a) : "l"(p));
    return a;
}

__global__ void __launch_bounds__(NTHR) fused_loss_kernel(
    const float* __restrict__ gt_img,
    const float* __restrict__ gt_seg,
    const float* __restrict__ inr_output,
    const float* __restrict__ seg_output,
    const float* __restrict__ inr_features,
    const int* __restrict__ a_idx,
    const int* __restrict__ p_idx,
    const int* __restrict__ n_idx,
    float* __restrict__ out)
{
    __shared__ alignas(128) float sx[ROWS_PER_BLK * CCLS];   // 10 KB
    __shared__ alignas(128) float sg[ROWS_PER_BLK * CCLS];   // 10 KB
    __shared__ alignas(8) unsigned long long mbar;
    __shared__ float sm[NTHR / 32];
    __shared__ bool  s_last;

    const int tid  = threadIdx.x;
    const int bid  = blockIdx.x;
    const int lane = tid & 31;
    const uint32_t mb = smem_u32(&mbar);

    // ---- mbarrier init ----------------------------------------------------
    if (tid == 0) {
        asm volatile("mbarrier.init.shared::cta.b64 [%0], 1;" :: "r"(mb) : "memory");
    }
    __syncthreads();

    // ---- issue bulk async copies for the CE streams (single thread) -------
    if (tid == 0) {
        asm volatile("mbarrier.arrive.expect_tx.shared::cta.b64 _, [%0], %1;"
                     :: "r"(mb), "r"(2 * CE_BYTES) : "memory");
        const char* gx = (const char*)seg_output + (size_t)bid * CE_BYTES;
        const char* gg = (const char*)gt_seg     + (size_t)bid * CE_BYTES;
        asm volatile(
            "cp.async.bulk.shared::cta.global.mbarrier::complete_tx::bytes "
            "[%0], [%1], %2, [%3];"
            :: "r"(smem_u32(sx)), "l"(gx), "r"(CE_BYTES), "r"(mb) : "memory");
        asm volatile(
            "cp.async.bulk.shared::cta.global.mbarrier::complete_tx::bytes "
            "[%0], [%1], %2, [%3];"
            :: "r"(smem_u32(sg)), "l"(gg), "r"(CE_BYTES), "r"(mb) : "memory");
    }

    float acc = 0.0f;

    // ---- MSE via LDG (overlaps with bulk copies) --------------------------
    if (tid < MSE_PER_BLK) {
        const float4* io4 = (const float4*)inr_output + bid * MSE_PER_BLK;
        const float4* gi4 = (const float4*)gt_img     + bid * MSE_PER_BLK;
        float4 a = io4[tid];
        float4 b = gi4[tid];
        float dx = a.x - b.x, dy = a.y - b.y, dz = a.z - b.z, dw = a.w - b.w;
        acc += (dx * dx + dy * dy + dz * dz + dw * dw)
             * (1.0f / (float)(NPTS * 3));
    }

    // ---- Triplet: warp per triplet (first 4096 global warps) --------------
    {
        const int gw = bid * (NTHR / 32) + (tid >> 5);   // 0..8191
        if (gw < TTRI) {
            const int ia = a_idx[gw], ip = p_idx[gw], in_ = n_idx[gw];
            float2 av = ((const float2*)(inr_features + (size_t)ia * DFEAT))[lane];
            float2 pv = ((const float2*)(inr_features + (size_t)ip * DFEAT))[lane];
            float2 nv = ((const float2*)(inr_features + (size_t)in_ * DFEAT))[lane];
            float dpx = av.x - pv.x, dpy = av.y - pv.y;
            float dnx = av.x - nv.x, dny = av.y - nv.y;
            float dp = dpx * dpx + dpy * dpy;
            float dn = dnx * dnx + dny * dny;
            #pragma unroll
            for (int o = 16; o > 0; o >>= 1) {
                dp += __shfl_xor_sync(0xffffffff, dp, o);
                dn += __shfl_xor_sync(0xffffffff, dn, o);
            }
            if (lane == 0) acc += fmaxf(sqrtf(dp) - sqrtf(dn), 0.0f);
        }
    }

    // ---- wait for bulk copies (acquire) -----------------------------------
    asm volatile(
        "{\n\t"
        ".reg .pred P;\n"
        "W%=:\n\t"
        "mbarrier.try_wait.parity.acquire.cta.shared::cta.b64 P, [%0], 0;\n\t"
        "@!P bra W%=;\n\t"
        "}"
        :: "r"(mb) : "memory");

    // ---- CE compute: one row per thread from smem -------------------------
    {
        const float2* x2 = (const float2*)(sx + tid * CCLS);
        const float2* g2 = (const float2*)(sg + tid * CCLS);
        float x[CCLS], g[CCLS];
        #pragma unroll
        for (int j = 0; j < CCLS / 2; j++) {
            float2 v = x2[j]; x[2 * j] = v.x; x[2 * j + 1] = v.y;
            float2 w = g2[j]; g[2 * j] = w.x; g[2 * j + 1] = w.y;
        }
        // inputs are N(0,1): __expf safe without max-shift
        float se = 0.0f, dot = 0.0f, gs = 0.0f;
        #pragma unroll
        for (int c = 0; c < CCLS; c++) {
            se  += __expf(x[c]);
            dot += g[c] * x[c];
            gs  += g[c];
        }
        acc += (gs * __logf(se) - dot) * (1.0f / (float)NPTS);
    }

    // ---- Block reduce -----------------------------------------------------
    #pragma unroll
    for (int o = 16; o > 0; o >>= 1)
        acc += __shfl_xor_sync(0xffffffff, acc, o);
    const int wid = tid >> 5;
    if (lane == 0) sm[wid] = acc;
    __syncthreads();
    if (wid == 0) {
        float v = (lane < (NTHR >> 5)) ? sm[lane] : 0.0f;
        #pragma unroll
        for (int o = 16; o > 0; o >>= 1)
            v += __shfl_xor_sync(0xffffffff, v, o);
        if (lane == 0) {
            g_partials[bid] = v;
            __threadfence();
            unsigned prev = atomicAdd(&g_count, 1u);
            s_last = (prev == NBLK - 1);
        }
    }
    __syncthreads();

    // ---- Last block: sum 1024 partials, write out, reset counter ----------
    if (s_last) {
        volatile float* gp = g_partials;
        float v = gp[tid] + gp[tid + NTHR] + gp[tid + 2 * NTHR] + gp[tid + 3 * NTHR];
        #pragma unroll
        for (int o = 16; o > 0; o >>= 1)
            v += __shfl_xor_sync(0xffffffff, v, o);
        if (lane == 0) sm[wid] = v;
        __syncthreads();
        if (wid == 0) {
            float w = (lane < (NTHR >> 5)) ? sm[lane] : 0.0f;
            #pragma unroll
            for (int o = 16; o > 0; o >>= 1)
                w += __shfl_xor_sync(0xffffffff, w, o);
            if (lane == 0) {
                out[0] = w;
                __threadfence();
                g_count = 0;              // reset for next replay
            }
        }
    }
}

extern "C" void kernel_launch(void* const* d_in, const int* in_sizes, int n_in,
                              void* d_out, int out_size) {
    const float* gt_img       = (const float*)d_in[0];
    const float* gt_seg       = (const float*)d_in[1];
    const float* inr_output   = (const float*)d_in[2];
    const float* seg_output   = (const float*)d_in[3];
    const float* inr_features = (const float*)d_in[4];
    const int*   a_idx        = (const int*)d_in[5];
    const int*   p_idx        = (const int*)d_in[6];
    const int*   n_idx        = (const int*)d_in[7];
    float* out = (float*)d_out;

    fused_loss_kernel<<<NBLK, NTHR>>>(gt_img, gt_seg, inr_output, seg_output,
                                      inr_features, a_idx, p_idx, n_idx, out);
}

// round 9
// speedup vs baseline: 1.0717x; 1.0717x over previous
#include <cuda_runtime.h>

#define NPTS 262144
#define CCLS 10
#define DFEAT 64
#define TTRI 4096

#define NTHR 256
#define NBLK 1024
#define MSE_N4 196608   // 3N/4 float4-pairs

__global__ void __launch_bounds__(NTHR, 4) fused_loss_kernel(
    const float* __restrict__ gt_img,
    const float* __restrict__ gt_seg,
    const float* __restrict__ inr_output,
    const float* __restrict__ seg_output,
    const float* __restrict__ inr_features,
    const int* __restrict__ a_idx,
    const int* __restrict__ p_idx,
    const int* __restrict__ n_idx,
    float* __restrict__ out)
{
    const int tid  = threadIdx.x;
    const int bid  = blockIdx.x;
    const int gtid = bid * NTHR + tid;      // 0..262143
    const int lane = tid & 31;

    // =================== FRONT-BATCHED LOADS ===============================
    // ---- triplet indices first (gathers depend on them) -------------------
    const int  gw      = gtid >> 5;          // global warp id, 0..8191
    const bool do_tri  = gw < TTRI;
    int ia = 0, ip = 0, in_ = 0;
    if (do_tri) { ia = a_idx[gw]; ip = p_idx[gw]; in_ = n_idx[gw]; }

    // ---- triplet feature gathers (3 x LDG.64) ------------------------------
    float2 av = {0.f, 0.f}, pv = {0.f, 0.f}, nv = {0.f, 0.f};
    if (do_tri) {
        av = ((const float2*)(inr_features + (size_t)ia  * DFEAT))[lane];
        pv = ((const float2*)(inr_features + (size_t)ip  * DFEAT))[lane];
        nv = ((const float2*)(inr_features + (size_t)in_ * DFEAT))[lane];
    }

    // ---- MSE loads (2 x LDG.128) -------------------------------------------
    const bool do_mse = gtid < MSE_N4;
    float4 ma = {0.f, 0.f, 0.f, 0.f}, mb = {0.f, 0.f, 0.f, 0.f};
    if (do_mse) {
        ma = ((const float4*)inr_output)[gtid];
        mb = ((const float4*)gt_img)[gtid];
    }

    // ---- CE loads: one row per thread (10 x LDG.64) ------------------------
    float x[CCLS], g[CCLS];
    {
        const float2* x2 = (const float2*)(seg_output + (size_t)gtid * CCLS);
        const float2* g2 = (const float2*)(gt_seg     + (size_t)gtid * CCLS);
        #pragma unroll
        for (int j = 0; j < CCLS / 2; j++) {
            float2 v = x2[j]; x[2 * j] = v.x; x[2 * j + 1] = v.y;
            float2 w = g2[j]; g[2 * j] = w.x; g[2 * j + 1] = w.y;
        }
    }

    // =================== COMPUTE ===========================================
    float acc = 0.0f;

    // ---- MSE ---------------------------------------------------------------
    {
        float dx = ma.x - mb.x, dy = ma.y - mb.y;
        float dz = ma.z - mb.z, dw = ma.w - mb.w;
        acc += (dx * dx + dy * dy + dz * dz + dw * dw)
             * (1.0f / (float)(NPTS * 3));
    }

    // ---- CE (inputs N(0,1): __expf safe without max-shift) -----------------
    {
        float se = 0.0f, dot = 0.0f, gs = 0.0f;
        #pragma unroll
        for (int c = 0; c < CCLS; c++) {
            se  += __expf(x[c]);
            dot += g[c] * x[c];
            gs  += g[c];
        }
        acc += (gs * __logf(se) - dot) * (1.0f / (float)NPTS);
    }

    // ---- Triplet ------------------------------------------------------------
    {
        float dpx = av.x - pv.x, dpy = av.y - pv.y;
        float dnx = av.x - nv.x, dny = av.y - nv.y;
        float dp = dpx * dpx + dpy * dpy;
        float dn = dnx * dnx + dny * dny;
        #pragma unroll
        for (int o = 16; o > 0; o >>= 1) {
            dp += __shfl_xor_sync(0xffffffff, dp, o);
            dn += __shfl_xor_sync(0xffffffff, dn, o);
        }
        if (do_tri && lane == 0)
            acc += fmaxf(sqrtf(dp) - sqrtf(dn), 0.0f);
    }

    // ---- Block reduce + one atomic per block --------------------------------
    __shared__ float sm[NTHR / 32];
    #pragma unroll
    for (int o = 16; o > 0; o >>= 1)
        acc += __shfl_xor_sync(0xffffffff, acc, o);
    const int wid = tid >> 5;
    if (lane == 0) sm[wid] = acc;
    __syncthreads();
    if (wid == 0) {
        float v = (lane < (NTHR >> 5)) ? sm[lane] : 0.0f;
        #pragma unroll
        for (int o = 16; o > 0; o >>= 1)
            v += __shfl_xor_sync(0xffffffff, v, o);
        if (lane == 0) atomicAdd(out, v);
    }
}

extern "C" void kernel_launch(void* const* d_in, const int* in_sizes, int n_in,
                              void* d_out, int out_size) {
    const float* gt_img       = (const float*)d_in[0];
    const float* gt_seg       = (const float*)d_in[1];
    const float* inr_output   = (const float*)d_in[2];
    const float* seg_output   = (const float*)d_in[3];
    const float* inr_features = (const float*)d_in[4];
    const int*   a_idx        = (const int*)d_in[5];
    const int*   p_idx        = (const int*)d_in[6];
    const int*   n_idx        = (const int*)d_in[7];
    float* out = (float*)d_out;

    cudaMemsetAsync(out, 0, sizeof(float));
    fused_loss_kernel<<<NBLK, NTHR>>>(gt_img, gt_seg, inr_output, seg_output,
                                      inr_features, a_idx, p_idx, n_idx, out);
}

// round 10
// speedup vs baseline: 1.1061x; 1.0322x over previous
#include <cuda_runtime.h>

#define NPTS 262144
#define CCLS 10
#define DFEAT 64
#define TTRI 4096

#define NTHR 256
#define NBLK 1024
#define MSE_N4 196608   // 3N/4 float4-pairs

__global__ void __launch_bounds__(NTHR, 4) fused_loss_kernel(
    const float* __restrict__ gt_img,
    const float* __restrict__ gt_seg,
    const float* __restrict__ inr_output,
    const float* __restrict__ seg_output,
    const float* __restrict__ inr_features,
    const int* __restrict__ a_idx,
    const int* __restrict__ p_idx,
    const int* __restrict__ n_idx,
    float* __restrict__ out)
{
    const int tid  = threadIdx.x;
    const int bid  = blockIdx.x;
    const int gtid = bid * NTHR + tid;      // 0..262143
    const int lane = tid & 31;

    // =================== FRONT-BATCHED LOADS ===============================
    // ---- triplet indices first (gathers depend on them) -------------------
    const int  gw      = gtid >> 5;          // global warp id, 0..8191
    const bool do_tri  = gw < TTRI;
    int ia = 0, ip = 0, in_ = 0;
    if (do_tri) { ia = a_idx[gw]; ip = p_idx[gw]; in_ = n_idx[gw]; }

    // ---- triplet feature gathers (3 x LDG.64) ------------------------------
    float2 av = {0.f, 0.f}, pv = {0.f, 0.f}, nv = {0.f, 0.f};
    if (do_tri) {
        av = ((const float2*)(inr_features + (size_t)ia  * DFEAT))[lane];
        pv = ((const float2*)(inr_features + (size_t)ip  * DFEAT))[lane];
        nv = ((const float2*)(inr_features + (size_t)in_ * DFEAT))[lane];
    }

    // ---- MSE loads (2 x LDG.128) -------------------------------------------
    const bool do_mse = gtid < MSE_N4;
    float4 ma = {0.f, 0.f, 0.f, 0.f}, mb = {0.f, 0.f, 0.f, 0.f};
    if (do_mse) {
        ma = ((const float4*)inr_output)[gtid];
        mb = ((const float4*)gt_img)[gtid];
    }

    // ---- CE loads: one row per thread (10 x LDG.64) ------------------------
    float x[CCLS], g[CCLS];
    {
        const float2* x2 = (const float2*)(seg_output + (size_t)gtid * CCLS);
        const float2* g2 = (const float2*)(gt_seg     + (size_t)gtid * CCLS);
        #pragma unroll
        for (int j = 0; j < CCLS / 2; j++) {
            float2 v = x2[j]; x[2 * j] = v.x; x[2 * j + 1] = v.y;
            float2 w = g2[j]; g[2 * j] = w.x; g[2 * j + 1] = w.y;
        }
    }

    // =================== COMPUTE ===========================================
    float acc = 0.0f;

    // ---- MSE ---------------------------------------------------------------
    {
        float dx = ma.x - mb.x, dy = ma.y - mb.y;
        float dz = ma.z - mb.z, dw = ma.w - mb.w;
        acc += (dx * dx + dy * dy + dz * dz + dw * dw)
             * (1.0f / (float)(NPTS * 3));
    }

    // ---- CE (inputs N(0,1): __expf safe without max-shift) -----------------
    {
        float se = 0.0f, dot = 0.0f, gs = 0.0f;
        #pragma unroll
        for (int c = 0; c < CCLS; c++) {
            se  += __expf(x[c]);
            dot += g[c] * x[c];
            gs  += g[c];
        }
        acc += (gs * __logf(se) - dot) * (1.0f / (float)NPTS);
    }

    // ---- Triplet ------------------------------------------------------------
    {
        float dpx = av.x - pv.x, dpy = av.y - pv.y;
        float dnx = av.x - nv.x, dny = av.y - nv.y;
        float dp = dpx * dpx + dpy * dpy;
        float dn = dnx * dnx + dny * dny;
        #pragma unroll
        for (int o = 16; o > 0; o >>= 1) {
            dp += __shfl_xor_sync(0xffffffff, dp, o);
            dn += __shfl_xor_sync(0xffffffff, dn, o);
        }
        if (do_tri && lane == 0)
            acc += fmaxf(sqrtf(dp) - sqrtf(dn), 0.0f);
    }

    // ---- Block reduce + one atomic per block --------------------------------
    __shared__ float sm[NTHR / 32];
    #pragma unroll
    for (int o = 16; o > 0; o >>= 1)
        acc += __shfl_xor_sync(0xffffffff, acc, o);
    const int wid = tid >> 5;
    if (lane == 0) sm[wid] = acc;
    __syncthreads();
    if (wid == 0) {
        float v = (lane < (NTHR >> 5)) ? sm[lane] : 0.0f;
        #pragma unroll
        for (int o = 16; o > 0; o >>= 1)
            v += __shfl_xor_sync(0xffffffff, v, o);
        if (lane == 0) atomicAdd(out, v);
    }
}

extern "C" void kernel_launch(void* const* d_in, const int* in_sizes, int n_in,
                              void* d_out, int out_size) {
    const float* gt_img       = (const float*)d_in[0];
    const float* gt_seg       = (const float*)d_in[1];
    const float* inr_output   = (const float*)d_in[2];
    const float* seg_output   = (const float*)d_in[3];
    const float* inr_features = (const float*)d_in[4];
    const int*   a_idx        = (const int*)d_in[5];
    const int*   p_idx        = (const int*)d_in[6];
    const int*   n_idx        = (const int*)d_in[7];
    float* out = (float*)d_out;

    cudaMemsetAsync(out, 0, sizeof(float));
    fused_loss_kernel<<<NBLK, NTHR>>>(gt_img, gt_seg, inr_output, seg_output,
                                      inr_features, a_idx, p_idx, n_idx, out);
}

// round 11
// speedup vs baseline: 1.1205x; 1.0130x over previous
#include <cuda_runtime.h>

#define NPTS 262144
#define CCLS 10
#define DFEAT 64
#define TTRI 4096

#define NTHR 256
#define NBLK 1024
#define MSE_N4 196608   // 3N/4 float4-pairs

__global__ void __launch_bounds__(NTHR, 4) fused_loss_kernel(
    const float* __restrict__ gt_img,
    const float* __restrict__ gt_seg,
    const float* __restrict__ inr_output,
    const float* __restrict__ seg_output,
    const float* __restrict__ inr_features,
    const int* __restrict__ a_idx,
    const int* __restrict__ p_idx,
    const int* __restrict__ n_idx,
    float* __restrict__ out)
{
    const int tid  = threadIdx.x;
    const int bid  = blockIdx.x;
    const int gtid = bid * NTHR + tid;      // 0..262143
    const int lane = tid & 31;

    // =================== FRONT-BATCHED LOADS ===============================
    // ---- triplet indices first (gathers depend on them) -------------------
    const int  gw      = gtid >> 5;          // global warp id, 0..8191
    const bool do_tri  = gw < TTRI;
    int ia = 0, ip = 0, in_ = 0;
    if (do_tri) { ia = a_idx[gw]; ip = p_idx[gw]; in_ = n_idx[gw]; }

    // ---- triplet feature gathers (3 x LDG.64) ------------------------------
    float2 av = {0.f, 0.f}, pv = {0.f, 0.f}, nv = {0.f, 0.f};
    if (do_tri) {
        av = ((const float2*)(inr_features + (size_t)ia  * DFEAT))[lane];
        pv = ((const float2*)(inr_features + (size_t)ip  * DFEAT))[lane];
        nv = ((const float2*)(inr_features + (size_t)in_ * DFEAT))[lane];
    }

    // ---- MSE loads (2 x LDG.128) -------------------------------------------
    const bool do_mse = gtid < MSE_N4;
    float4 ma = {0.f, 0.f, 0.f, 0.f}, mb = {0.f, 0.f, 0.f, 0.f};
    if (do_mse) {
        ma = ((const float4*)inr_output)[gtid];
        mb = ((const float4*)gt_img)[gtid];
    }

    // ---- CE loads: one row per thread (10 x LDG.64) ------------------------
    float x[CCLS], g[CCLS];
    {
        const float2* x2 = (const float2*)(seg_output + (size_t)gtid * CCLS);
        const float2* g2 = (const float2*)(gt_seg     + (size_t)gtid * CCLS);
        #pragma unroll
        for (int j = 0; j < CCLS / 2; j++) {
            float2 v = x2[j]; x[2 * j] = v.x; x[2 * j + 1] = v.y;
            float2 w = g2[j]; g[2 * j] = w.x; g[2 * j + 1] = w.y;
        }
    }

    // =================== COMPUTE ===========================================
    float acc = 0.0f;

    // ---- MSE ---------------------------------------------------------------
    {
        float dx = ma.x - mb.x, dy = ma.y - mb.y;
        float dz = ma.z - mb.z, dw = ma.w - mb.w;
        acc += (dx * dx + dy * dy + dz * dz + dw * dw)
             * (1.0f / (float)(NPTS * 3));
    }

    // ---- CE (inputs N(0,1): __expf safe without max-shift) -----------------
    {
        float se = 0.0f, dot = 0.0f, gs = 0.0f;
        #pragma unroll
        for (int c = 0; c < CCLS; c++) {
            se  += __expf(x[c]);
            dot += g[c] * x[c];
            gs  += g[c];
        }
        acc += (gs * __logf(se) - dot) * (1.0f / (float)NPTS);
    }

    // ---- Triplet ------------------------------------------------------------
    {
        float dpx = av.x - pv.x, dpy = av.y - pv.y;
        float dnx = av.x - nv.x, dny = av.y - nv.y;
        float dp = dpx * dpx + dpy * dpy;
        float dn = dnx * dnx + dny * dny;
        #pragma unroll
        for (int o = 16; o > 0; o >>= 1) {
            dp += __shfl_xor_sync(0xffffffff, dp, o);
            dn += __shfl_xor_sync(0xffffffff, dn, o);
        }
        if (do_tri && lane == 0)
            acc += fmaxf(sqrtf(dp) - sqrtf(dn), 0.0f);
    }

    // ---- Block reduce + one atomic per block --------------------------------
    __shared__ float sm[NTHR / 32];
    #pragma unroll
    for (int o = 16; o > 0; o >>= 1)
        acc += __shfl_xor_sync(0xffffffff, acc, o);
    const int wid = tid >> 5;
    if (lane == 0) sm[wid] = acc;
    __syncthreads();
    if (wid == 0) {
        float v = (lane < (NTHR >> 5)) ? sm[lane] : 0.0f;
        #pragma unroll
        for (int o = 16; o > 0; o >>= 1)
            v += __shfl_xor_sync(0xffffffff, v, o);
        if (lane == 0) atomicAdd(out, v);
    }
}

extern "C" void kernel_launch(void* const* d_in, const int* in_sizes, int n_in,
                              void* d_out, int out_size) {
    const float* gt_img       = (const float*)d_in[0];
    const float* gt_seg       = (const float*)d_in[1];
    const float* inr_output   = (const float*)d_in[2];
    const float* seg_output   = (const float*)d_in[3];
    const float* inr_features = (const float*)d_in[4];
    const int*   a_idx        = (const int*)d_in[5];
    const int*   p_idx        = (const int*)d_in[6];
    const int*   n_idx        = (const int*)d_in[7];
    float* out = (float*)d_out;

    cudaMemsetAsync(out, 0, sizeof(float));
    fused_loss_kernel<<<NBLK, NTHR>>>(gt_img, gt_seg, inr_output, seg_output,
                                      inr_features, a_idx, p_idx, n_idx, out);
}